// round 2
// baseline (speedup 1.0000x reference)
#include <cuda_runtime.h>

#define BB   32
#define TT   512
#define HHD  512
#define KVD  1024
#define OUTD 128
#define XKD  1152   // OUT + KV
#define SDEC 128

// ---------------- static scratch ----------------
__device__ float g_key[BB*TT*KVD];            // 67 MB
__device__ float g_val[BB*TT*KVD];            // 67 MB
__device__ float g_q[BB*KVD];
__device__ float g_scores[BB*TT];
__device__ float g_xT[(XKD/4)*BB*4];          // x=[y,ctx] grouped-4 transposed
__device__ float g_h0T[2][(HHD/4)*BB*4];      // ping-pong
__device__ float g_h1T[2][(HHD/4)*BB*4];
__device__ float g_c0[HHD*BB];                // [u][b]
__device__ float g_c1[HHD*BB];

__device__ __forceinline__ float fast_tanh(float x) {
    float e = __expf(2.0f * x);
    return 1.0f - __fdividef(2.0f, e + 1.0f);
}
__device__ __forceinline__ float sigm(float x) {
    return __fdividef(1.0f, 1.0f + __expf(-x));
}
__device__ __forceinline__ float dot4(float4 a, float4 b) {
    return a.x*b.x + a.y*b.y + a.z*b.z + a.w*b.w;
}
// grouped-4 transposed float index for (k, batch m)
__device__ __forceinline__ int idx4(int k, int m) { return ((k >> 2) << 7) + (m << 2) + (k & 3); }

// ---------------------------------------------------------------
// init: blocks 0..31 -> q0 = h0[0] @ Wq^T ; blocks 32..39 -> state transpose + y0=0
// ---------------------------------------------------------------
__global__ void init_kernel(const float* __restrict__ h0, const float* __restrict__ c0,
                            const float* __restrict__ Wq) {
    int bx = blockIdx.x, tid = threadIdx.x;
    if (bx < 32) {
        __shared__ float sh[512];
        for (int p = tid; p < 512; p += 256) sh[p] = h0[bx * 512 + p];
        __syncthreads();
        int w = tid >> 5, lane = tid & 31;
        const float4* shv = (const float4*)sh;
        for (int jj = 0; jj < 128; jj++) {
            int j = (w << 7) + jj;
            const float4* wq = (const float4*)(Wq + (size_t)j * 512);
            float acc = 0.f;
#pragma unroll
            for (int i = 0; i < 4; i++)
                acc += dot4(__ldg(&wq[lane + (i << 5)]), shv[lane + (i << 5)]);
#pragma unroll
            for (int off = 16; off; off >>= 1) acc += __shfl_xor_sync(0xffffffffu, acc, off);
            if (lane == 0) g_q[(bx << 10) + j] = acc;
        }
    } else {
        int p0 = (bx - 32) * 256 + tid;
        for (int i = p0; i < BB * HHD; i += 8 * 256) {
            int b = i >> 9, u = i & 511;
            int ix = idx4(u, b);
            g_h0T[0][ix] = h0[i];
            g_h1T[0][ix] = h0[BB * HHD + i];
            g_c0[u * 32 + b] = c0[i];
            g_c1[u * 32 + b] = c0[BB * HHD + i];
        }
        for (int i = p0; i < OUTD * 32; i += 8 * 256) g_xT[i] = 0.f;
    }
}

// ---------------------------------------------------------------
// key/value precompute: C[16384,1024] = A @ W^T, 128x128x16 tiles
// ---------------------------------------------------------------
__global__ void __launch_bounds__(256) gemm_kv_kernel(const float* __restrict__ A,
                                                      const float* __restrict__ Wk,
                                                      const float* __restrict__ Wv) {
    const float* W = blockIdx.z ? Wv : Wk;
    float* C = blockIdx.z ? g_val : g_key;
    __shared__ float As[16][132];
    __shared__ float Ws[16][132];
    int tid = threadIdx.x;
    int tx = tid & 15, ty = tid >> 4;
    int m0 = blockIdx.y << 7, n0 = blockIdx.x << 7;
    int lr = tid >> 2, lc = (tid & 3) << 2;
    float acc[8][8];
#pragma unroll
    for (int i = 0; i < 8; i++)
#pragma unroll
        for (int j = 0; j < 8; j++) acc[i][j] = 0.f;

    for (int k0 = 0; k0 < 1024; k0 += 16) {
        float4 a0 = *(const float4*)(A + (size_t)(m0 + lr) * 1024 + k0 + lc);
        float4 a1 = *(const float4*)(A + (size_t)(m0 + lr + 64) * 1024 + k0 + lc);
        float4 w0 = *(const float4*)(W + (size_t)(n0 + lr) * 1024 + k0 + lc);
        float4 w1 = *(const float4*)(W + (size_t)(n0 + lr + 64) * 1024 + k0 + lc);
        As[lc+0][lr] = a0.x; As[lc+1][lr] = a0.y; As[lc+2][lr] = a0.z; As[lc+3][lr] = a0.w;
        As[lc+0][lr+64] = a1.x; As[lc+1][lr+64] = a1.y; As[lc+2][lr+64] = a1.z; As[lc+3][lr+64] = a1.w;
        Ws[lc+0][lr] = w0.x; Ws[lc+1][lr] = w0.y; Ws[lc+2][lr] = w0.z; Ws[lc+3][lr] = w0.w;
        Ws[lc+0][lr+64] = w1.x; Ws[lc+1][lr+64] = w1.y; Ws[lc+2][lr+64] = w1.z; Ws[lc+3][lr+64] = w1.w;
        __syncthreads();
#pragma unroll
        for (int kk = 0; kk < 16; kk++) {
            float4 av0 = *(const float4*)&As[kk][ty * 8];
            float4 av1 = *(const float4*)&As[kk][ty * 8 + 4];
            float4 wv0 = *(const float4*)&Ws[kk][tx * 8];
            float4 wv1 = *(const float4*)&Ws[kk][tx * 8 + 4];
            float av[8] = {av0.x, av0.y, av0.z, av0.w, av1.x, av1.y, av1.z, av1.w};
            float wv[8] = {wv0.x, wv0.y, wv0.z, wv0.w, wv1.x, wv1.y, wv1.z, wv1.w};
#pragma unroll
            for (int i = 0; i < 8; i++)
#pragma unroll
                for (int j = 0; j < 8; j++) acc[i][j] += av[i] * wv[j];
        }
        __syncthreads();
    }
#pragma unroll
    for (int i = 0; i < 8; i++) {
        float* cr = C + (size_t)(m0 + ty * 8 + i) * 1024 + n0 + tx * 8;
        *(float4*)cr       = make_float4(acc[i][0], acc[i][1], acc[i][2], acc[i][3]);
        *(float4*)(cr + 4) = make_float4(acc[i][4], acc[i][5], acc[i][6], acc[i][7]);
    }
}

// ---------------------------------------------------------------
// scores[b][t] = sum_k We[k] * tanh(q[b][k] + key[b][t][k])
// grid (8 t-chunks, 32 b), 256 threads, warp handles 8 t rows
// ---------------------------------------------------------------
__global__ void scores_kernel(const float* __restrict__ We) {
    int b = blockIdx.y, chunk = blockIdx.x, tid = threadIdx.x;
    __shared__ float sq[1024], swe[1024];
    for (int p = tid; p < 1024; p += 256) { sq[p] = g_q[(b << 10) + p]; swe[p] = We[p]; }
    __syncthreads();
    int w = tid >> 5, lane = tid & 31;
    const float4* qv = (const float4*)sq;
    const float4* wv = (const float4*)swe;
#pragma unroll
    for (int r = 0; r < 8; r++) {
        int t = (chunk << 6) + (w << 3) + r;
        const float4* kp = (const float4*)(g_key + ((size_t)(b * 512 + t) << 10));
        float acc = 0.f;
#pragma unroll 4
        for (int k4 = lane; k4 < 256; k4 += 32) {
            float4 kk = __ldg(&kp[k4]);
            float4 qq = qv[k4];
            float4 ww = wv[k4];
            acc += ww.x * fast_tanh(qq.x + kk.x);
            acc += ww.y * fast_tanh(qq.y + kk.y);
            acc += ww.z * fast_tanh(qq.z + kk.z);
            acc += ww.w * fast_tanh(qq.w + kk.w);
        }
#pragma unroll
        for (int off = 16; off; off >>= 1) acc += __shfl_xor_sync(0xffffffffu, acc, off);
        if (lane == 0) g_scores[(b << 9) + t] = acc;
    }
}

// ---------------------------------------------------------------
// softmax (redundant per block) + context; writes ctx into g_xT (k = 128+d)
// grid (4 d-chunks of 256, 32 b), 256 threads
// ---------------------------------------------------------------
__global__ void ctx_kernel() {
    int b = blockIdx.y, tid = threadIdx.x;
    __shared__ float sal[512];
    __shared__ float red[256];
    float v0 = g_scores[(b << 9) + tid];
    float v1 = g_scores[(b << 9) + 256 + tid];
    red[tid] = fmaxf(v0, v1);
    __syncthreads();
    for (int s = 128; s > 0; s >>= 1) {
        if (tid < s) red[tid] = fmaxf(red[tid], red[tid + s]);
        __syncthreads();
    }
    float mx = red[0];
    __syncthreads();
    float e0 = __expf(v0 - mx), e1 = __expf(v1 - mx);
    sal[tid] = e0; sal[tid + 256] = e1;
    red[tid] = e0 + e1;
    __syncthreads();
    for (int s = 128; s > 0; s >>= 1) {
        if (tid < s) red[tid] += red[tid + s];
        __syncthreads();
    }
    float inv = __fdividef(1.0f, red[0]);

    int d = (blockIdx.x << 8) + tid;
    const float* vp = g_val + ((size_t)b << 19) + d;   // b*512*1024 + d
    float acc = 0.f;
#pragma unroll 4
    for (int t = 0; t < 512; t++)
        acc += sal[t] * __ldg(vp + ((size_t)t << 10));
    g_xT[(32 + (d >> 2)) * 128 + (b << 2) + (d & 3)] = acc * inv;
}

// ---------------------------------------------------------------
// lstm0: grid 512 (unit u), block 128 (4 warps split k), fused cell update
// ---------------------------------------------------------------
__global__ void lstm0_kernel(const float* __restrict__ wih, const float* __restrict__ whh,
                             const float* __restrict__ bih, const float* __restrict__ bhh,
                             int p) {
    __shared__ float part[4][4][32];
    int u = blockIdx.x, w = threadIdx.x >> 5, lane = threadIdx.x & 31;
    const float4* xT4 = (const float4*)g_xT;
    const float4* hT4 = (const float4*)g_h0T[p];
    const float4* wihv = (const float4*)wih;   // 288 f4 per row
    const float4* whhv = (const float4*)whh;   // 128 f4 per row
    float acc[4] = {0.f, 0.f, 0.f, 0.f};

    for (int g = w * 72; g < w * 72 + 72; g++) {
        float4 xv = xT4[(g << 5) + lane];
#pragma unroll
        for (int gate = 0; gate < 4; gate++)
            acc[gate] += dot4(__ldg(&wihv[(size_t)(gate * 512 + u) * 288 + g]), xv);
    }
    for (int g = w * 32; g < w * 32 + 32; g++) {
        float4 hv = hT4[(g << 5) + lane];
#pragma unroll
        for (int gate = 0; gate < 4; gate++)
            acc[gate] += dot4(__ldg(&whhv[(size_t)(gate * 512 + u) * 128 + g]), hv);
    }
#pragma unroll
    for (int gate = 0; gate < 4; gate++) part[gate][w][lane] = acc[gate];
    __syncthreads();
    if (w == 0) {
        float gv[4];
#pragma unroll
        for (int gate = 0; gate < 4; gate++) {
            int j = gate * 512 + u;
            gv[gate] = part[gate][0][lane] + part[gate][1][lane] +
                       part[gate][2][lane] + part[gate][3][lane] + bih[j] + bhh[j];
        }
        float c = g_c0[u * 32 + lane];
        float cn = sigm(gv[1]) * c + sigm(gv[0]) * fast_tanh(gv[2]);
        float hn = sigm(gv[3]) * fast_tanh(cn);
        g_c0[u * 32 + lane] = cn;
        g_h0T[1 - p][idx4(u, lane)] = hn;
    }
}

// ---------------------------------------------------------------
// lstm1 (+ q-projection for next step): blocks<512 lstm, >=512 qproj
// ---------------------------------------------------------------
__global__ void lstm1q_kernel(const float* __restrict__ wih, const float* __restrict__ whh,
                              const float* __restrict__ bih, const float* __restrict__ bhh,
                              const float* __restrict__ Wq, int p) {
    int w = threadIdx.x >> 5, lane = threadIdx.x & 31;
    const float4* h0n = (const float4*)g_h0T[1 - p];
    if (blockIdx.x < 512) {
        __shared__ float part[4][4][32];
        int u = blockIdx.x;
        const float4* hT4 = (const float4*)g_h1T[p];
        const float4* wihv = (const float4*)wih;   // 128 f4 per row
        const float4* whhv = (const float4*)whh;
        float acc[4] = {0.f, 0.f, 0.f, 0.f};
        for (int g = w * 32; g < w * 32 + 32; g++) {
            float4 xv = h0n[(g << 5) + lane];
            float4 hv = hT4[(g << 5) + lane];
#pragma unroll
            for (int gate = 0; gate < 4; gate++) {
                int j = gate * 512 + u;
                acc[gate] += dot4(__ldg(&wihv[(size_t)j * 128 + g]), xv);
                acc[gate] += dot4(__ldg(&whhv[(size_t)j * 128 + g]), hv);
            }
        }
#pragma unroll
        for (int gate = 0; gate < 4; gate++) part[gate][w][lane] = acc[gate];
        __syncthreads();
        if (w == 0) {
            float gv[4];
#pragma unroll
            for (int gate = 0; gate < 4; gate++) {
                int j = gate * 512 + u;
                gv[gate] = part[gate][0][lane] + part[gate][1][lane] +
                           part[gate][2][lane] + part[gate][3][lane] + bih[j] + bhh[j];
            }
            float c = g_c1[u * 32 + lane];
            float cn = sigm(gv[1]) * c + sigm(gv[0]) * fast_tanh(gv[2]);
            float hn = sigm(gv[3]) * fast_tanh(cn);
            g_c1[u * 32 + lane] = cn;
            g_h1T[1 - p][idx4(u, lane)] = hn;
        }
    } else {
        // q projection: q = h0n @ Wq^T, one warp per output feature j
        int j = (blockIdx.x - 512) * 4 + w;
        const float4* wq = (const float4*)(Wq + (size_t)j * 512);
        float acc = 0.f;
        for (int g = 0; g < 128; g++)
            acc += dot4(__ldg(&wq[g]), h0n[(g << 5) + lane]);
        g_q[lane * 1024 + j] = acc;
    }
}

// ---------------------------------------------------------------
// fc: y_hat = relu(h1n @ fc_w^T + b); write out[b,s,:]; y_next = 1+y_hat into xT
// grid 16, block 256, warp per output o
// ---------------------------------------------------------------
__global__ void fc_kernel(const float* __restrict__ fc_w, const float* __restrict__ fc_b,
                          float* __restrict__ out, int s, int p) {
    int w = threadIdx.x >> 5, lane = threadIdx.x & 31;
    int o = blockIdx.x * 8 + w;
    const float4* h1n = (const float4*)g_h1T[1 - p];
    const float4* fw = (const float4*)(fc_w + (size_t)o * 512);
    float acc = 0.f;
    for (int g = 0; g < 128; g++)
        acc += dot4(__ldg(&fw[g]), h1n[(g << 5) + lane]);
    float y = fmaxf(acc + fc_b[o], 0.f);
    out[(size_t)lane * (SDEC * OUTD) + s * OUTD + o] = y;
    g_xT[idx4(o, lane)] = 1.0f + y;
}

// ---------------------------------------------------------------
extern "C" void kernel_launch(void* const* d_in, const int* in_sizes, int n_in,
                              void* d_out, int out_size) {
    const float* enc  = (const float*)d_in[0];
    const float* h0   = (const float*)d_in[1];
    const float* c0   = (const float*)d_in[2];
    const float* Wk   = (const float*)d_in[3];
    const float* Wq   = (const float*)d_in[4];
    const float* Wv   = (const float*)d_in[5];
    const float* We   = (const float*)d_in[6];
    const float* wih0 = (const float*)d_in[7];
    const float* whh0 = (const float*)d_in[8];
    const float* bih0 = (const float*)d_in[9];
    const float* bhh0 = (const float*)d_in[10];
    const float* wih1 = (const float*)d_in[11];
    const float* whh1 = (const float*)d_in[12];
    const float* bih1 = (const float*)d_in[13];
    const float* bhh1 = (const float*)d_in[14];
    const float* fc_w = (const float*)d_in[15];
    const float* fc_b = (const float*)d_in[16];
    float* out = (float*)d_out;

    init_kernel<<<40, 256>>>(h0, c0, Wq);
    gemm_kv_kernel<<<dim3(8, 128, 2), 256>>>(enc, Wk, Wv);

    for (int s = 0; s < SDEC; s++) {
        int p = s & 1;
        scores_kernel<<<dim3(8, 32), 256>>>(We);
        ctx_kernel<<<dim3(4, 32), 256>>>();
        lstm0_kernel<<<512, 128>>>(wih0, whh0, bih0, bhh0, p);
        lstm1q_kernel<<<768, 128>>>(wih1, whh1, bih1, bhh1, Wq, p);
        fc_kernel<<<16, 256>>>(fc_w, fc_b, out, s, p);
    }
}

// round 3
// speedup vs baseline: 1.4985x; 1.4985x over previous
#include <cuda_runtime.h>

#define BB   32
#define TT   512
#define HHD  512
#define KVD  1024
#define OUTD 128
#define XKD  1152   // OUT + KV
#define SDEC 128

// ---------------- static scratch ----------------
__device__ float g_key[BB*TT*KVD];            // 67 MB
__device__ float g_val[BB*TT*KVD];            // 67 MB
__device__ float g_q[BB*KVD];
__device__ float g_scores[BB*TT];
__device__ float g_xT[(XKD/4)*BB*4];          // x=[y,ctx] grouped-4 transposed
__device__ float g_h0T[2][(HHD/4)*BB*4];      // ping-pong
__device__ float g_h1T[2][(HHD/4)*BB*4];
__device__ float g_c0[HHD*BB];                // [u][b]
__device__ float g_c1[HHD*BB];

__device__ __forceinline__ float fast_tanh(float x) {
    float e = __expf(2.0f * x);
    return 1.0f - __fdividef(2.0f, e + 1.0f);
}
__device__ __forceinline__ float sigm(float x) {
    return __fdividef(1.0f, 1.0f + __expf(-x));
}
__device__ __forceinline__ float dot4(float4 a, float4 b) {
    return a.x*b.x + a.y*b.y + a.z*b.z + a.w*b.w;
}
// grouped-4 transposed float index for (k, batch m)
__device__ __forceinline__ int idx4(int k, int m) { return ((k >> 2) << 7) + (m << 2) + (k & 3); }

// ---------------------------------------------------------------
// init: blocks 0..31 -> q0 = h0[0] @ Wq^T ; blocks 32..39 -> state transpose + y0=0
// ---------------------------------------------------------------
__global__ void init_kernel(const float* __restrict__ h0, const float* __restrict__ c0,
                            const float* __restrict__ Wq) {
    int bx = blockIdx.x, tid = threadIdx.x;
    if (bx < 32) {
        __shared__ float sh[512];
        for (int p = tid; p < 512; p += 256) sh[p] = h0[bx * 512 + p];
        __syncthreads();
        int w = tid >> 5, lane = tid & 31;
        const float4* shv = (const float4*)sh;
        for (int jj = 0; jj < 128; jj++) {
            int j = (w << 7) + jj;
            const float4* wq = (const float4*)(Wq + (size_t)j * 512);
            float acc = 0.f;
#pragma unroll
            for (int i = 0; i < 4; i++)
                acc += dot4(__ldg(&wq[lane + (i << 5)]), shv[lane + (i << 5)]);
#pragma unroll
            for (int off = 16; off; off >>= 1) acc += __shfl_xor_sync(0xffffffffu, acc, off);
            if (lane == 0) g_q[(bx << 10) + j] = acc;
        }
    } else {
        int p0 = (bx - 32) * 256 + tid;
        for (int i = p0; i < BB * HHD; i += 8 * 256) {
            int b = i >> 9, u = i & 511;
            int ix = idx4(u, b);
            g_h0T[0][ix] = h0[i];
            g_h1T[0][ix] = h0[BB * HHD + i];
            g_c0[u * 32 + b] = c0[i];
            g_c1[u * 32 + b] = c0[BB * HHD + i];
        }
        for (int i = p0; i < OUTD * 32; i += 8 * 256) g_xT[i] = 0.f;
    }
}

// ---------------------------------------------------------------
// key/value precompute: C[16384,1024] = A @ W^T, 128x128x16 tiles
// ---------------------------------------------------------------
__global__ void __launch_bounds__(256) gemm_kv_kernel(const float* __restrict__ A,
                                                      const float* __restrict__ Wk,
                                                      const float* __restrict__ Wv) {
    const float* W = blockIdx.z ? Wv : Wk;
    float* C = blockIdx.z ? g_val : g_key;
    __shared__ float As[16][132];
    __shared__ float Ws[16][132];
    int tid = threadIdx.x;
    int tx = tid & 15, ty = tid >> 4;
    int m0 = blockIdx.y << 7, n0 = blockIdx.x << 7;
    int lr = tid >> 2, lc = (tid & 3) << 2;
    float acc[8][8];
#pragma unroll
    for (int i = 0; i < 8; i++)
#pragma unroll
        for (int j = 0; j < 8; j++) acc[i][j] = 0.f;

    for (int k0 = 0; k0 < 1024; k0 += 16) {
        float4 a0 = *(const float4*)(A + (size_t)(m0 + lr) * 1024 + k0 + lc);
        float4 a1 = *(const float4*)(A + (size_t)(m0 + lr + 64) * 1024 + k0 + lc);
        float4 w0 = *(const float4*)(W + (size_t)(n0 + lr) * 1024 + k0 + lc);
        float4 w1 = *(const float4*)(W + (size_t)(n0 + lr + 64) * 1024 + k0 + lc);
        As[lc+0][lr] = a0.x; As[lc+1][lr] = a0.y; As[lc+2][lr] = a0.z; As[lc+3][lr] = a0.w;
        As[lc+0][lr+64] = a1.x; As[lc+1][lr+64] = a1.y; As[lc+2][lr+64] = a1.z; As[lc+3][lr+64] = a1.w;
        Ws[lc+0][lr] = w0.x; Ws[lc+1][lr] = w0.y; Ws[lc+2][lr] = w0.z; Ws[lc+3][lr] = w0.w;
        Ws[lc+0][lr+64] = w1.x; Ws[lc+1][lr+64] = w1.y; Ws[lc+2][lr+64] = w1.z; Ws[lc+3][lr+64] = w1.w;
        __syncthreads();
#pragma unroll
        for (int kk = 0; kk < 16; kk++) {
            float4 av0 = *(const float4*)&As[kk][ty * 8];
            float4 av1 = *(const float4*)&As[kk][ty * 8 + 4];
            float4 wv0 = *(const float4*)&Ws[kk][tx * 8];
            float4 wv1 = *(const float4*)&Ws[kk][tx * 8 + 4];
            float av[8] = {av0.x, av0.y, av0.z, av0.w, av1.x, av1.y, av1.z, av1.w};
            float wv[8] = {wv0.x, wv0.y, wv0.z, wv0.w, wv1.x, wv1.y, wv1.z, wv1.w};
#pragma unroll
            for (int i = 0; i < 8; i++)
#pragma unroll
                for (int j = 0; j < 8; j++) acc[i][j] += av[i] * wv[j];
        }
        __syncthreads();
    }
#pragma unroll
    for (int i = 0; i < 8; i++) {
        float* cr = C + (size_t)(m0 + ty * 8 + i) * 1024 + n0 + tx * 8;
        *(float4*)cr       = make_float4(acc[i][0], acc[i][1], acc[i][2], acc[i][3]);
        *(float4*)(cr + 4) = make_float4(acc[i][4], acc[i][5], acc[i][6], acc[i][7]);
    }
}

// ---------------------------------------------------------------
// scores[b][t] = sum_k We[k] * tanh(q[b][k] + key[b][t][k])
// grid (16 t-chunks, 32 b), 256 threads; warp handles 4 rows,
// inner k-loop fully unrolled (8 outstanding float4 LDGs)
// ---------------------------------------------------------------
__global__ void __launch_bounds__(256) scores_kernel(const float* __restrict__ We) {
    int b = blockIdx.y, chunk = blockIdx.x, tid = threadIdx.x;
    __shared__ float sq[1024], swe[1024];
    for (int p = tid; p < 1024; p += 256) { sq[p] = g_q[(b << 10) + p]; swe[p] = We[p]; }
    __syncthreads();
    int w = tid >> 5, lane = tid & 31;
    const float4* qv = (const float4*)sq;
    const float4* wv = (const float4*)swe;
#pragma unroll
    for (int r = 0; r < 4; r++) {
        int t = (chunk << 5) + (w << 2) + r;
        const float4* kp = (const float4*)(g_key + ((size_t)(b * 512 + t) << 10));
        float4 kk[8];
#pragma unroll
        for (int i = 0; i < 8; i++) kk[i] = __ldg(&kp[lane + (i << 5)]);
        float acc = 0.f;
#pragma unroll
        for (int i = 0; i < 8; i++) {
            float4 qq = qv[lane + (i << 5)];
            float4 ww = wv[lane + (i << 5)];
            acc += ww.x * fast_tanh(qq.x + kk[i].x);
            acc += ww.y * fast_tanh(qq.y + kk[i].y);
            acc += ww.z * fast_tanh(qq.z + kk[i].z);
            acc += ww.w * fast_tanh(qq.w + kk[i].w);
        }
#pragma unroll
        for (int off = 16; off; off >>= 1) acc += __shfl_xor_sync(0xffffffffu, acc, off);
        if (lane == 0) g_scores[(b << 9) + t] = acc;
    }
}

// ---------------------------------------------------------------
// softmax (redundant per block) + context into g_xT
// grid (16 d-chunks of 64, 32 b), 512 threads: tid = tpar*64 + dlocal
// each thread sums t = tpar, tpar+8, ... (64 iters, unroll 8)
// ---------------------------------------------------------------
__global__ void __launch_bounds__(512) ctx_kernel() {
    int b = blockIdx.y, tid = threadIdx.x;
    __shared__ float sal[512];
    __shared__ float red[512];
    float v = g_scores[(b << 9) + tid];
    red[tid] = v;
    __syncthreads();
#pragma unroll
    for (int s = 256; s > 0; s >>= 1) {
        if (tid < s) red[tid] = fmaxf(red[tid], red[tid + s]);
        __syncthreads();
    }
    float mx = red[0];
    __syncthreads();
    float e = __expf(v - mx);
    sal[tid] = e;
    red[tid] = e;
    __syncthreads();
#pragma unroll
    for (int s = 256; s > 0; s >>= 1) {
        if (tid < s) red[tid] += red[tid + s];
        __syncthreads();
    }
    float inv = __fdividef(1.0f, red[0]);
    __syncthreads();

    int dl = tid & 63;
    int tpar = tid >> 6;                       // 0..7
    int d = (blockIdx.x << 6) + dl;
    const float* vp = g_val + ((size_t)b << 19) + d;
    float acc = 0.f;
#pragma unroll 8
    for (int t = tpar; t < 512; t += 8)
        acc += sal[t] * __ldg(vp + ((size_t)t << 10));
    red[tid] = acc;
    __syncthreads();
    if (tid < 256) red[tid] += red[tid + 256];
    __syncthreads();
    if (tid < 128) red[tid] += red[tid + 128];
    __syncthreads();
    if (tid < 64) {
        float r = (red[tid] + red[tid + 64]) * inv;
        g_xT[(32 + (d >> 2)) * 128 + (b << 2) + (d & 3)] = r;
    }
}

// ---------------------------------------------------------------
// lstm0: grid 512 (unit u), block 128 (4 warps split k), fused cell update
// ---------------------------------------------------------------
__global__ void lstm0_kernel(const float* __restrict__ wih, const float* __restrict__ whh,
                             const float* __restrict__ bih, const float* __restrict__ bhh,
                             int p) {
    __shared__ float part[4][4][32];
    int u = blockIdx.x, w = threadIdx.x >> 5, lane = threadIdx.x & 31;
    const float4* xT4 = (const float4*)g_xT;
    const float4* hT4 = (const float4*)g_h0T[p];
    const float4* wihv = (const float4*)wih;   // 288 f4 per row
    const float4* whhv = (const float4*)whh;   // 128 f4 per row
    float acc[4] = {0.f, 0.f, 0.f, 0.f};

    for (int g = w * 72; g < w * 72 + 72; g++) {
        float4 xv = xT4[(g << 5) + lane];
#pragma unroll
        for (int gate = 0; gate < 4; gate++)
            acc[gate] += dot4(__ldg(&wihv[(size_t)(gate * 512 + u) * 288 + g]), xv);
    }
    for (int g = w * 32; g < w * 32 + 32; g++) {
        float4 hv = hT4[(g << 5) + lane];
#pragma unroll
        for (int gate = 0; gate < 4; gate++)
            acc[gate] += dot4(__ldg(&whhv[(size_t)(gate * 512 + u) * 128 + g]), hv);
    }
#pragma unroll
    for (int gate = 0; gate < 4; gate++) part[gate][w][lane] = acc[gate];
    __syncthreads();
    if (w == 0) {
        float gv[4];
#pragma unroll
        for (int gate = 0; gate < 4; gate++) {
            int j = gate * 512 + u;
            gv[gate] = part[gate][0][lane] + part[gate][1][lane] +
                       part[gate][2][lane] + part[gate][3][lane] + bih[j] + bhh[j];
        }
        float c = g_c0[u * 32 + lane];
        float cn = sigm(gv[1]) * c + sigm(gv[0]) * fast_tanh(gv[2]);
        float hn = sigm(gv[3]) * fast_tanh(cn);
        g_c0[u * 32 + lane] = cn;
        g_h0T[1 - p][idx4(u, lane)] = hn;
    }
}

// ---------------------------------------------------------------
// lstm1 (+ q-projection for next step): blocks<512 lstm, >=512 qproj
// ---------------------------------------------------------------
__global__ void lstm1q_kernel(const float* __restrict__ wih, const float* __restrict__ whh,
                              const float* __restrict__ bih, const float* __restrict__ bhh,
                              const float* __restrict__ Wq, int p) {
    int w = threadIdx.x >> 5, lane = threadIdx.x & 31;
    const float4* h0n = (const float4*)g_h0T[1 - p];
    if (blockIdx.x < 512) {
        __shared__ float part[4][4][32];
        int u = blockIdx.x;
        const float4* hT4 = (const float4*)g_h1T[p];
        const float4* wihv = (const float4*)wih;   // 128 f4 per row
        const float4* whhv = (const float4*)whh;
        float acc[4] = {0.f, 0.f, 0.f, 0.f};
        for (int g = w * 32; g < w * 32 + 32; g++) {
            float4 xv = h0n[(g << 5) + lane];
            float4 hv = hT4[(g << 5) + lane];
#pragma unroll
            for (int gate = 0; gate < 4; gate++) {
                int j = gate * 512 + u;
                acc[gate] += dot4(__ldg(&wihv[(size_t)j * 128 + g]), xv);
                acc[gate] += dot4(__ldg(&whhv[(size_t)j * 128 + g]), hv);
            }
        }
#pragma unroll
        for (int gate = 0; gate < 4; gate++) part[gate][w][lane] = acc[gate];
        __syncthreads();
        if (w == 0) {
            float gv[4];
#pragma unroll
            for (int gate = 0; gate < 4; gate++) {
                int j = gate * 512 + u;
                gv[gate] = part[gate][0][lane] + part[gate][1][lane] +
                           part[gate][2][lane] + part[gate][3][lane] + bih[j] + bhh[j];
            }
            float c = g_c1[u * 32 + lane];
            float cn = sigm(gv[1]) * c + sigm(gv[0]) * fast_tanh(gv[2]);
            float hn = sigm(gv[3]) * fast_tanh(cn);
            g_c1[u * 32 + lane] = cn;
            g_h1T[1 - p][idx4(u, lane)] = hn;
        }
    } else {
        // q projection: q = h0n @ Wq^T, one warp per output feature j
        int j = (blockIdx.x - 512) * 4 + w;
        const float4* wq = (const float4*)(Wq + (size_t)j * 512);
        float acc = 0.f;
        for (int g = 0; g < 128; g++)
            acc += dot4(__ldg(&wq[g]), h0n[(g << 5) + lane]);
        g_q[lane * 1024 + j] = acc;
    }
}

// ---------------------------------------------------------------
// fc: y_hat = relu(h1n @ fc_w^T + b); write out[b,s,:]; y_next = 1+y_hat into xT
// grid 16, block 256, warp per output o
// ---------------------------------------------------------------
__global__ void fc_kernel(const float* __restrict__ fc_w, const float* __restrict__ fc_b,
                          float* __restrict__ out, int s, int p) {
    int w = threadIdx.x >> 5, lane = threadIdx.x & 31;
    int o = blockIdx.x * 8 + w;
    const float4* h1n = (const float4*)g_h1T[1 - p];
    const float4* fw = (const float4*)(fc_w + (size_t)o * 512);
    float acc = 0.f;
    for (int g = 0; g < 128; g++)
        acc += dot4(__ldg(&fw[g]), h1n[(g << 5) + lane]);
    float y = fmaxf(acc + fc_b[o], 0.f);
    out[(size_t)lane * (SDEC * OUTD) + s * OUTD + o] = y;
    g_xT[idx4(o, lane)] = 1.0f + y;
}

// ---------------------------------------------------------------
extern "C" void kernel_launch(void* const* d_in, const int* in_sizes, int n_in,
                              void* d_out, int out_size) {
    const float* enc  = (const float*)d_in[0];
    const float* h0   = (const float*)d_in[1];
    const float* c0   = (const float*)d_in[2];
    const float* Wk   = (const float*)d_in[3];
    const float* Wq   = (const float*)d_in[4];
    const float* Wv   = (const float*)d_in[5];
    const float* We   = (const float*)d_in[6];
    const float* wih0 = (const float*)d_in[7];
    const float* whh0 = (const float*)d_in[8];
    const float* bih0 = (const float*)d_in[9];
    const float* bhh0 = (const float*)d_in[10];
    const float* wih1 = (const float*)d_in[11];
    const float* whh1 = (const float*)d_in[12];
    const float* bih1 = (const float*)d_in[13];
    const float* bhh1 = (const float*)d_in[14];
    const float* fc_w = (const float*)d_in[15];
    const float* fc_b = (const float*)d_in[16];
    float* out = (float*)d_out;

    init_kernel<<<40, 256>>>(h0, c0, Wq);
    gemm_kv_kernel<<<dim3(8, 128, 2), 256>>>(enc, Wk, Wv);

    for (int s = 0; s < SDEC; s++) {
        int p = s & 1;
        scores_kernel<<<dim3(16, 32), 256>>>(We);
        ctx_kernel<<<dim3(16, 32), 512>>>();
        lstm0_kernel<<<512, 128>>>(wih0, whh0, bih0, bhh0, p);
        lstm1q_kernel<<<768, 128>>>(wih1, whh1, bih1, bhh1, Wq, p);
        fc_kernel<<<16, 256>>>(fc_w, fc_b, out, s, p);
    }
}

// round 4
// speedup vs baseline: 2.1708x; 1.4486x over previous
#include <cuda_runtime.h>

#define BB   32
#define TT   512
#define HHD  512
#define KVD  1024
#define OUTD 128
#define XKD  1152   // OUT + KV
#define SDEC 128

// ---------------- static scratch ----------------
__device__ float g_key[BB*TT*KVD];            // 67 MB
__device__ float g_val[BB*TT*KVD];            // 67 MB
__device__ float g_q[BB*KVD];
__device__ float g_scores[BB*TT];
__device__ float g_xT[(XKD/4)*BB*4];          // x=[y,ctx] grouped-4 transposed
__device__ float g_h0T[2][(HHD/4)*BB*4];      // ping-pong
__device__ float g_h1T[2][(HHD/4)*BB*4];
__device__ float g_c0[HHD*BB];                // [u][b]
__device__ float g_c1[HHD*BB];

__device__ __forceinline__ float fast_tanh(float x) {
    float e = __expf(2.0f * x);
    return 1.0f - __fdividef(2.0f, e + 1.0f);
}
__device__ __forceinline__ float sigm(float x) {
    return __fdividef(1.0f, 1.0f + __expf(-x));
}
__device__ __forceinline__ float dot4(float4 a, float4 b) {
    return a.x*b.x + a.y*b.y + a.z*b.z + a.w*b.w;
}
// grouped-4 transposed float index for (k, batch m)
__device__ __forceinline__ int idx4(int k, int m) { return ((k >> 2) << 7) + (m << 2) + (k & 3); }

// ---------------------------------------------------------------
// init: blocks 0..31 -> q0 = h0[0] @ Wq^T ; blocks 32..39 -> state transpose + y0=0
// ---------------------------------------------------------------
__global__ void init_kernel(const float* __restrict__ h0, const float* __restrict__ c0,
                            const float* __restrict__ Wq) {
    int bx = blockIdx.x, tid = threadIdx.x;
    if (bx < 32) {
        __shared__ float sh[512];
        for (int p = tid; p < 512; p += 256) sh[p] = h0[bx * 512 + p];
        __syncthreads();
        int w = tid >> 5, lane = tid & 31;
        const float4* shv = (const float4*)sh;
        for (int jj = 0; jj < 128; jj++) {
            int j = (w << 7) + jj;
            const float4* wq = (const float4*)(Wq + (size_t)j * 512);
            float acc = 0.f;
#pragma unroll
            for (int i = 0; i < 4; i++)
                acc += dot4(__ldg(&wq[lane + (i << 5)]), shv[lane + (i << 5)]);
#pragma unroll
            for (int off = 16; off; off >>= 1) acc += __shfl_xor_sync(0xffffffffu, acc, off);
            if (lane == 0) g_q[(bx << 10) + j] = acc;
        }
    } else {
        int p0 = (bx - 32) * 256 + tid;
        for (int i = p0; i < BB * HHD; i += 8 * 256) {
            int b = i >> 9, u = i & 511;
            int ix = idx4(u, b);
            g_h0T[0][ix] = h0[i];
            g_h1T[0][ix] = h0[BB * HHD + i];
            g_c0[u * 32 + b] = c0[i];
            g_c1[u * 32 + b] = c0[BB * HHD + i];
        }
        for (int i = p0; i < OUTD * 32; i += 8 * 256) g_xT[i] = 0.f;
    }
}

// ---------------------------------------------------------------
// key/value precompute: C[16384,1024] = A @ W^T, 128x128x16 tiles
// ---------------------------------------------------------------
__global__ void __launch_bounds__(256) gemm_kv_kernel(const float* __restrict__ A,
                                                      const float* __restrict__ Wk,
                                                      const float* __restrict__ Wv) {
    const float* W = blockIdx.z ? Wv : Wk;
    float* C = blockIdx.z ? g_val : g_key;
    __shared__ float As[16][132];
    __shared__ float Ws[16][132];
    int tid = threadIdx.x;
    int tx = tid & 15, ty = tid >> 4;
    int m0 = blockIdx.y << 7, n0 = blockIdx.x << 7;
    int lr = tid >> 2, lc = (tid & 3) << 2;
    float acc[8][8];
#pragma unroll
    for (int i = 0; i < 8; i++)
#pragma unroll
        for (int j = 0; j < 8; j++) acc[i][j] = 0.f;

    for (int k0 = 0; k0 < 1024; k0 += 16) {
        float4 a0 = *(const float4*)(A + (size_t)(m0 + lr) * 1024 + k0 + lc);
        float4 a1 = *(const float4*)(A + (size_t)(m0 + lr + 64) * 1024 + k0 + lc);
        float4 w0 = *(const float4*)(W + (size_t)(n0 + lr) * 1024 + k0 + lc);
        float4 w1 = *(const float4*)(W + (size_t)(n0 + lr + 64) * 1024 + k0 + lc);
        As[lc+0][lr] = a0.x; As[lc+1][lr] = a0.y; As[lc+2][lr] = a0.z; As[lc+3][lr] = a0.w;
        As[lc+0][lr+64] = a1.x; As[lc+1][lr+64] = a1.y; As[lc+2][lr+64] = a1.z; As[lc+3][lr+64] = a1.w;
        Ws[lc+0][lr] = w0.x; Ws[lc+1][lr] = w0.y; Ws[lc+2][lr] = w0.z; Ws[lc+3][lr] = w0.w;
        Ws[lc+0][lr+64] = w1.x; Ws[lc+1][lr+64] = w1.y; Ws[lc+2][lr+64] = w1.z; Ws[lc+3][lr+64] = w1.w;
        __syncthreads();
#pragma unroll
        for (int kk = 0; kk < 16; kk++) {
            float4 av0 = *(const float4*)&As[kk][ty * 8];
            float4 av1 = *(const float4*)&As[kk][ty * 8 + 4];
            float4 wv0 = *(const float4*)&Ws[kk][tx * 8];
            float4 wv1 = *(const float4*)&Ws[kk][tx * 8 + 4];
            float av[8] = {av0.x, av0.y, av0.z, av0.w, av1.x, av1.y, av1.z, av1.w};
            float wv[8] = {wv0.x, wv0.y, wv0.z, wv0.w, wv1.x, wv1.y, wv1.z, wv1.w};
#pragma unroll
            for (int i = 0; i < 8; i++)
#pragma unroll
                for (int j = 0; j < 8; j++) acc[i][j] += av[i] * wv[j];
        }
        __syncthreads();
    }
#pragma unroll
    for (int i = 0; i < 8; i++) {
        float* cr = C + (size_t)(m0 + ty * 8 + i) * 1024 + n0 + tx * 8;
        *(float4*)cr       = make_float4(acc[i][0], acc[i][1], acc[i][2], acc[i][3]);
        *(float4*)(cr + 4) = make_float4(acc[i][4], acc[i][5], acc[i][6], acc[i][7]);
    }
}

// ---------------------------------------------------------------
// scores body: scores[b][t] = sum_k We[k]*tanh(q[b][k]+key[b][t][k])
// called with 256 threads; (chunk, b) identify 32-t slab
// ---------------------------------------------------------------
__device__ __forceinline__ void scores_body(const float* __restrict__ We,
                                            int chunk, int b, int tid,
                                            float* sq, float* swe) {
    for (int p = tid; p < 1024; p += 256) { sq[p] = g_q[(b << 10) + p]; swe[p] = We[p]; }
    __syncthreads();
    int w = tid >> 5, lane = tid & 31;
    const float4* qv = (const float4*)sq;
    const float4* wv = (const float4*)swe;
#pragma unroll
    for (int r = 0; r < 4; r++) {
        int t = (chunk << 5) + (w << 2) + r;
        const float4* kp = (const float4*)(g_key + ((size_t)(b * 512 + t) << 10));
        float4 kk[8];
#pragma unroll
        for (int i = 0; i < 8; i++) kk[i] = __ldg(&kp[lane + (i << 5)]);
        float acc = 0.f;
#pragma unroll
        for (int i = 0; i < 8; i++) {
            float4 qq = qv[lane + (i << 5)];
            float4 ww = wv[lane + (i << 5)];
            acc += ww.x * fast_tanh(qq.x + kk[i].x);
            acc += ww.y * fast_tanh(qq.y + kk[i].y);
            acc += ww.z * fast_tanh(qq.z + kk[i].z);
            acc += ww.w * fast_tanh(qq.w + kk[i].w);
        }
#pragma unroll
        for (int off = 16; off; off >>= 1) acc += __shfl_xor_sync(0xffffffffu, acc, off);
        if (lane == 0) g_scores[(b << 9) + t] = acc;
    }
}

__global__ void __launch_bounds__(256) scores_kernel(const float* __restrict__ We) {
    __shared__ float sq[1024], swe[1024];
    scores_body(We, blockIdx.x, blockIdx.y, threadIdx.x, sq, swe);
}

// ---------------------------------------------------------------
// softmax (redundant per block) + context into g_xT
// grid (16 d-chunks of 64, 32 b), 512 threads
// ---------------------------------------------------------------
__global__ void __launch_bounds__(512) ctx_kernel() {
    int b = blockIdx.y, tid = threadIdx.x;
    __shared__ float sal[512];
    __shared__ float red[512];
    float v = g_scores[(b << 9) + tid];
    red[tid] = v;
    __syncthreads();
#pragma unroll
    for (int s = 256; s > 0; s >>= 1) {
        if (tid < s) red[tid] = fmaxf(red[tid], red[tid + s]);
        __syncthreads();
    }
    float mx = red[0];
    __syncthreads();
    float e = __expf(v - mx);
    sal[tid] = e;
    red[tid] = e;
    __syncthreads();
#pragma unroll
    for (int s = 256; s > 0; s >>= 1) {
        if (tid < s) red[tid] += red[tid + s];
        __syncthreads();
    }
    float inv = __fdividef(1.0f, red[0]);
    __syncthreads();

    int dl = tid & 63;
    int tpar = tid >> 6;                       // 0..7
    int d = (blockIdx.x << 6) + dl;
    const float* vp = g_val + ((size_t)b << 19) + d;
    float acc = 0.f;
#pragma unroll 8
    for (int t = tpar; t < 512; t += 8)
        acc += sal[t] * __ldg(vp + ((size_t)t << 10));
    red[tid] = acc;
    __syncthreads();
    if (tid < 256) red[tid] += red[tid + 256];
    __syncthreads();
    if (tid < 128) red[tid] += red[tid + 128];
    __syncthreads();
    if (tid < 64) {
        float r = (red[tid] + red[tid + 64]) * inv;
        g_xT[(32 + (d >> 2)) * 128 + (b << 2) + (d & 3)] = r;
    }
}

// ---------------------------------------------------------------
// lstm0: grid 512 (unit u), 256 threads (8 warps split k), fused cell update
// ---------------------------------------------------------------
__global__ void __launch_bounds__(256) lstm0_kernel(const float* __restrict__ wih,
                                                    const float* __restrict__ whh,
                                                    const float* __restrict__ bih,
                                                    const float* __restrict__ bhh,
                                                    int p) {
    __shared__ float part[4][8][32];
    int u = blockIdx.x, w = threadIdx.x >> 5, lane = threadIdx.x & 31;
    const float4* xT4 = (const float4*)g_xT;
    const float4* hT4 = (const float4*)g_h0T[p];
    const float4* wihv = (const float4*)wih;   // 288 f4 per row
    const float4* whhv = (const float4*)whh;   // 128 f4 per row
    float acc[4] = {0.f, 0.f, 0.f, 0.f};

    // ih: 288 groups split 8 ways -> 36 per warp
    for (int g = w * 36; g < w * 36 + 36; g++) {
        float4 xv = xT4[(g << 5) + lane];
#pragma unroll
        for (int gate = 0; gate < 4; gate++)
            acc[gate] += dot4(__ldg(&wihv[(size_t)(gate * 512 + u) * 288 + g]), xv);
    }
    // hh: 128 groups split 8 ways -> 16 per warp
    for (int g = w * 16; g < w * 16 + 16; g++) {
        float4 hv = hT4[(g << 5) + lane];
#pragma unroll
        for (int gate = 0; gate < 4; gate++)
            acc[gate] += dot4(__ldg(&whhv[(size_t)(gate * 512 + u) * 128 + g]), hv);
    }
#pragma unroll
    for (int gate = 0; gate < 4; gate++) part[gate][w][lane] = acc[gate];
    __syncthreads();
    if (w == 0) {
        float gv[4];
#pragma unroll
        for (int gate = 0; gate < 4; gate++) {
            int j = gate * 512 + u;
            float s = 0.f;
#pragma unroll
            for (int i = 0; i < 8; i++) s += part[gate][i][lane];
            gv[gate] = s + bih[j] + bhh[j];
        }
        float c = g_c0[u * 32 + lane];
        float cn = sigm(gv[1]) * c + sigm(gv[0]) * fast_tanh(gv[2]);
        float hn = sigm(gv[3]) * fast_tanh(cn);
        g_c0[u * 32 + lane] = cn;
        g_h0T[1 - p][idx4(u, lane)] = hn;
    }
}

// ---------------------------------------------------------------
// lstm1 (+ q-projection): blocks<512 lstm (256 thr, 8-way k), >=512 qproj (8 warps)
// ---------------------------------------------------------------
__global__ void __launch_bounds__(256) lstm1q_kernel(const float* __restrict__ wih,
                                                     const float* __restrict__ whh,
                                                     const float* __restrict__ bih,
                                                     const float* __restrict__ bhh,
                                                     const float* __restrict__ Wq, int p) {
    int w = threadIdx.x >> 5, lane = threadIdx.x & 31;
    const float4* h0n = (const float4*)g_h0T[1 - p];
    if (blockIdx.x < 512) {
        __shared__ float part[4][8][32];
        int u = blockIdx.x;
        const float4* hT4 = (const float4*)g_h1T[p];
        const float4* wihv = (const float4*)wih;   // 128 f4 per row
        const float4* whhv = (const float4*)whh;
        float acc[4] = {0.f, 0.f, 0.f, 0.f};
        for (int g = w * 16; g < w * 16 + 16; g++) {
            float4 xv = h0n[(g << 5) + lane];
            float4 hv = hT4[(g << 5) + lane];
#pragma unroll
            for (int gate = 0; gate < 4; gate++) {
                int j = gate * 512 + u;
                acc[gate] += dot4(__ldg(&wihv[(size_t)j * 128 + g]), xv);
                acc[gate] += dot4(__ldg(&whhv[(size_t)j * 128 + g]), hv);
            }
        }
#pragma unroll
        for (int gate = 0; gate < 4; gate++) part[gate][w][lane] = acc[gate];
        __syncthreads();
        if (w == 0) {
            float gv[4];
#pragma unroll
            for (int gate = 0; gate < 4; gate++) {
                int j = gate * 512 + u;
                float s = 0.f;
#pragma unroll
                for (int i = 0; i < 8; i++) s += part[gate][i][lane];
                gv[gate] = s + bih[j] + bhh[j];
            }
            float c = g_c1[u * 32 + lane];
            float cn = sigm(gv[1]) * c + sigm(gv[0]) * fast_tanh(gv[2]);
            float hn = sigm(gv[3]) * fast_tanh(cn);
            g_c1[u * 32 + lane] = cn;
            g_h1T[1 - p][idx4(u, lane)] = hn;
        }
    } else {
        // q projection: q = h0n @ Wq^T, one warp per output feature j (lane = batch)
        int j = (blockIdx.x - 512) * 8 + w;
        const float4* wq = (const float4*)(Wq + (size_t)j * 512);
        float acc = 0.f;
        for (int g = 0; g < 128; g++)
            acc += dot4(__ldg(&wq[g]), h0n[(g << 5) + lane]);
        g_q[lane * 1024 + j] = acc;
    }
}

// ---------------------------------------------------------------
// fused fc (this step) + scores (next step):
// blocks 0..15: y_hat = relu(h1n @ fc_w^T + b); out[b,s,:]; y_next into xT
// blocks 16..527: scores for the next step (reads g_q written by lstm1q)
// ---------------------------------------------------------------
__global__ void __launch_bounds__(256) fcscores_kernel(const float* __restrict__ fc_w,
                                                       const float* __restrict__ fc_b,
                                                       const float* __restrict__ We,
                                                       float* __restrict__ out, int s, int p) {
    __shared__ float sq[1024], swe[1024];
    if (blockIdx.x < 16) {
        int w = threadIdx.x >> 5, lane = threadIdx.x & 31;
        int o = blockIdx.x * 8 + w;
        const float4* h1n = (const float4*)g_h1T[1 - p];
        const float4* fw = (const float4*)(fc_w + (size_t)o * 512);
        float acc = 0.f;
        for (int g = 0; g < 128; g++)
            acc += dot4(__ldg(&fw[g]), h1n[(g << 5) + lane]);
        float y = fmaxf(acc + fc_b[o], 0.f);
        out[(size_t)lane * (SDEC * OUTD) + s * OUTD + o] = y;
        g_xT[idx4(o, lane)] = 1.0f + y;
    } else {
        int idx = blockIdx.x - 16;
        scores_body(We, idx & 15, idx >> 4, threadIdx.x, sq, swe);
    }
}

// ---------------------------------------------------------------
extern "C" void kernel_launch(void* const* d_in, const int* in_sizes, int n_in,
                              void* d_out, int out_size) {
    const float* enc  = (const float*)d_in[0];
    const float* h0   = (const float*)d_in[1];
    const float* c0   = (const float*)d_in[2];
    const float* Wk   = (const float*)d_in[3];
    const float* Wq   = (const float*)d_in[4];
    const float* Wv   = (const float*)d_in[5];
    const float* We   = (const float*)d_in[6];
    const float* wih0 = (const float*)d_in[7];
    const float* whh0 = (const float*)d_in[8];
    const float* bih0 = (const float*)d_in[9];
    const float* bhh0 = (const float*)d_in[10];
    const float* wih1 = (const float*)d_in[11];
    const float* whh1 = (const float*)d_in[12];
    const float* bih1 = (const float*)d_in[13];
    const float* bhh1 = (const float*)d_in[14];
    const float* fc_w = (const float*)d_in[15];
    const float* fc_b = (const float*)d_in[16];
    float* out = (float*)d_out;

    init_kernel<<<40, 256>>>(h0, c0, Wq);
    gemm_kv_kernel<<<dim3(8, 128, 2), 256>>>(enc, Wk, Wv);
    // scores for step 0 (uses q from init)
    scores_kernel<<<dim3(16, 32), 256>>>(We);

    for (int s = 0; s < SDEC; s++) {
        int p = s & 1;
        ctx_kernel<<<dim3(16, 32), 512>>>();
        lstm0_kernel<<<512, 256>>>(wih0, whh0, bih0, bhh0, p);
        lstm1q_kernel<<<640, 256>>>(wih1, whh1, bih1, bhh1, Wq, p);
        // fc for this step + scores for next step (last iteration's scores are unused)
        fcscores_kernel<<<528, 256>>>(fc_w, fc_b, We, out, s, p);
    }
}